// round 13
// baseline (speedup 1.0000x reference)
#include <cuda_runtime.h>
#include <cuda_bf16.h>
#include <math.h>

#define NTOT 131072
#define NF   512
#define DQ   128
#define NBAG 32
#define KC   32
#define SROW 80             // bytes per smem row (k5)

// k5 dynamic smem layout (4-stage ring)
#define K5_TB   10240                   // 128 rows * 80 B
#define K5_AW   (8 * K5_TB)             // float[128]
#define K5_BAG  (K5_AW + 512)           // int[128]
#define K5_RED  (K5_BAG + 512)          // float[2][128]
#define K5_SM   (K5_RED + 1024)         // 83968 B

// -------- scratch (static __device__ — no allocations allowed) ----------
__device__ __nv_bfloat16      g_fbf[(size_t)NTOT * NF];   // 128 MB bf16 feats
__device__ float              g_A[NTOT];                   // holds e = exp(A)
__device__ int                g_off[NBAG + 1];
__device__ unsigned long long g_crit[NBAG];
__device__ float              g_s[NBAG];
__device__ float              g_Bemb[NBAG * NF];
__device__ float              g_u[NBAG * NF];              // w_q @ Qc per bag
__device__ float              g_d0[NBAG];                  // b_q . Qc per bag
__device__ __nv_bfloat16      g_wvT[(size_t)NF * NF];      // [col][k]

// -------- helpers -----------------------------------------------------------
__device__ __forceinline__ unsigned fkey(float f) {
    unsigned u = __float_as_uint(f);
    return (u & 0x80000000u) ? ~u : (u | 0x80000000u);
}
__device__ __forceinline__ int find_bag(int n) {
    int lo = 0, hi = NBAG;
    while (hi - lo > 1) {
        int mid = (lo + hi) >> 1;
        if (n >= g_off[mid]) lo = mid; else hi = mid;
    }
    return lo;
}
__device__ __forceinline__ unsigned pk(float lo, float hi) {
    __nv_bfloat162 h = __floats2bfloat162_rn(lo, hi);
    return *(unsigned*)&h;
}
__device__ __forceinline__ void mma_bf16(float d[4], const unsigned a[4],
                                         unsigned b0, unsigned b1) {
    asm volatile(
        "mma.sync.aligned.m16n8k16.row.col.f32.bf16.bf16.f32 "
        "{%0,%1,%2,%3}, {%4,%5,%6,%7}, {%8,%9}, {%0,%1,%2,%3};"
        : "+f"(d[0]), "+f"(d[1]), "+f"(d[2]), "+f"(d[3])
        : "r"(a[0]), "r"(a[1]), "r"(a[2]), "r"(a[3]), "r"(b0), "r"(b1));
}
__device__ __forceinline__ void ldsm4(unsigned r[4], unsigned saddr) {
    asm volatile("ldmatrix.sync.aligned.m8n8.x4.shared.b16 {%0,%1,%2,%3}, [%4];"
                 : "=r"(r[0]), "=r"(r[1]), "=r"(r[2]), "=r"(r[3]) : "r"(saddr));
}
__device__ __forceinline__ void cp16(unsigned sdst, const void* gsrc) {
    asm volatile("cp.async.cg.shared.global [%0], [%1], 16;" :: "r"(sdst), "l"(gsrc));
}
__device__ __forceinline__ void cpcommit() { asm volatile("cp.async.commit_group;"); }
__device__ __forceinline__ void cpwait2()  { asm volatile("cp.async.wait_group 2;"); }

// -------- K0: prefix offsets + reset accumulators --------------------------
__global__ void k0_init(const int* __restrict__ sizes) {
    int t = threadIdx.x;
    if (t == 0) {
        int acc = 0;
        for (int i = 0; i < NBAG; i++) { g_off[i] = acc; acc += sizes[i]; }
        g_off[NBAG] = acc;
    }
    if (t < NBAG) { g_crit[t] = 0ull; g_s[t] = 0.f; }
    for (int i = t; i < NBAG * NF; i += blockDim.x) g_Bemb[i] = 0.f;
}

// -------- KT: transpose fp32 w_v [NF][NF] -> bf16 [col][k] -----------------
__global__ void kt_transpose(const float* __restrict__ src) {
    __shared__ float tile[32][33];
    int c0 = blockIdx.x * 32, r0 = blockIdx.y * 32;
    int x = threadIdx.x, y = threadIdx.y;  // (32,8)
#pragma unroll
    for (int i = 0; i < 32; i += 8)
        tile[y + i][x] = src[(size_t)(r0 + y + i) * NF + c0 + x];
    __syncthreads();
#pragma unroll
    for (int i = 0; i < 32; i += 8)
        g_wvT[(size_t)(c0 + y + i) * NF + r0 + x] = __float2bfloat16_rn(tile[x][y + i]);
}

// -------- K_PRE: feats fp32->bf16, c = feats@w_ins+b (fp32), fused crit ----
__global__ __launch_bounds__(256) void k_pre(
    const float* __restrict__ feats, const float* __restrict__ w_ins,
    const float* __restrict__ b_ins, float* __restrict__ out)
{
    __shared__ float wins[NF];
    int tid = threadIdx.x, lane = tid & 31, warp = tid >> 5;
    for (int i = tid; i < NF; i += 256) wins[i] = w_ins[i];
    __syncthreads();
    const float bi = __ldg(&b_ins[0]);
    const int base = blockIdx.x * 64 + warp * 8;
    int curBag = -1; unsigned curKey = 0u; unsigned curN = 0u;
#pragma unroll
    for (int rr = 0; rr < 8; rr++) {
        int n = base + rr;
        const float4* fp = (const float4*)&feats[(size_t)n * NF];
        uint2* dst = (uint2*)&g_fbf[(size_t)n * NF];
        float c = 0.f;
#pragma unroll
        for (int i = 0; i < 4; i++) {
            int idx = lane + i * 32;
            float4 v = fp[idx];
            int k = idx * 4;
            c = fmaf(v.x, wins[k], c);     c = fmaf(v.y, wins[k + 1], c);
            c = fmaf(v.z, wins[k + 2], c); c = fmaf(v.w, wins[k + 3], c);
            dst[idx] = make_uint2(pk(v.x, v.y), pk(v.z, v.w));
        }
#pragma unroll
        for (int o = 16; o > 0; o >>= 1) c += __shfl_xor_sync(0xFFFFFFFFu, c, o);
        if (lane == 0) {
            float cv = c + bi;
            out[NBAG + n] = cv;
            int bag = find_bag(n);
            unsigned k = fkey(cv);
            if (bag != curBag) {
                if (curBag >= 0)
                    atomicMax(&g_crit[curBag],
                              ((unsigned long long)curKey << 32) | curN);
                curBag = bag; curKey = k; curN = 0xFFFFFFFFu - (unsigned)n;
            } else if (k > curKey) {
                curKey = k; curN = 0xFFFFFFFFu - (unsigned)n;
            }
        }
    }
    if (lane == 0 && curBag >= 0)
        atomicMax(&g_crit[curBag], ((unsigned long long)curKey << 32) | curN);
}

// -------- K3B: per bag: Qc = feats[crit]@w_q + b_q; u = w_q@Qc; d0 = b_q.Qc
__global__ __launch_bounds__(512) void k3b(
    const float* __restrict__ feats, const float* __restrict__ w_q,
    const float* __restrict__ b_q)
{
    __shared__ float sf[NF];
    __shared__ float sq[DQ];
    __shared__ float part[4][DQ];
    const int b = blockIdx.x, t = threadIdx.x;
    const int lane = t & 31, warp = t >> 5;
    const int cr = (int)(0xFFFFFFFFu - (unsigned)(g_crit[b] & 0xFFFFFFFFull));

    if (t < NF) sf[t] = feats[(size_t)cr * NF + t];
    __syncthreads();

    // phase 1: Qc[col] — 4 k-quarters in parallel, coalesced across col
    {
        const int col = t & 127, kq = t >> 7;
        float q = 0.f;
        const float* wp = &w_q[(size_t)(kq * 128) * DQ + col];
        const float* fp = &sf[kq * 128];
#pragma unroll 8
        for (int k = 0; k < 128; k++) q = fmaf(fp[k], wp[(size_t)k * DQ], q);
        part[kq][col] = q;
    }
    __syncthreads();
    if (t < DQ) sq[t] = part[0][t] + part[1][t] + part[2][t] + part[3][t] + __ldg(&b_q[t]);
    __syncthreads();

    // phase 2: u[k] = w_q[k,:] . Qc — warp per row, lanes over columns
    for (int k = warp; k < NF; k += 16) {
        const float* wr = &w_q[(size_t)k * DQ];
        float s = 0.f;
#pragma unroll
        for (int c = 0; c < 4; c++)
            s = fmaf(wr[lane + 32 * c], sq[lane + 32 * c], s);
#pragma unroll
        for (int o = 16; o > 0; o >>= 1) s += __shfl_xor_sync(0xFFFFFFFFu, s, o);
        if (lane == 0) g_u[b * NF + k] = s;
    }

    // phase 3: d0 = b_q . Qc
    if (t < DQ) part[0][t] = __ldg(&b_q[t]) * sq[t];
    __syncthreads();
    if (t < 32) {
        float d = part[0][t] + part[0][t + 32] + part[0][t + 64] + part[0][t + 96];
#pragma unroll
        for (int o = 16; o > 0; o >>= 1) d += __shfl_xor_sync(0xFFFFFFFFu, d, o);
        if (t == 0) g_d0[b] = d;
    }
}

// -------- K4: e[n] = exp((feats[n].u[bag] + d0[bag])/sqrt(dq)); s[bag] += e
__global__ __launch_bounds__(256) void k4_scores() {
    const int warp = threadIdx.x >> 5, lane = threadIdx.x & 31;
    const int base = blockIdx.x * 64 + warp * 8;
    int curBag = -1; float curS = 0.f;
#pragma unroll
    for (int rr = 0; rr < 8; rr++) {
        int n = base + rr;
        int bag = find_bag(n);
        const uint4*  fp = (const uint4*)&g_fbf[(size_t)n * NF];
        const float4* up = (const float4*)&g_u[bag * NF];
        float p = 0.f;
#pragma unroll
        for (int i = 0; i < 2; i++) {
            uint4 fv = fp[lane * 2 + i];
            float4 u0 = up[lane * 4 + i * 2];
            float4 u1 = up[lane * 4 + i * 2 + 1];
            float2 f0 = __bfloat1622float2(*(__nv_bfloat162*)&fv.x);
            float2 f1 = __bfloat1622float2(*(__nv_bfloat162*)&fv.y);
            float2 f2 = __bfloat1622float2(*(__nv_bfloat162*)&fv.z);
            float2 f3 = __bfloat1622float2(*(__nv_bfloat162*)&fv.w);
            p = fmaf(f0.x, u0.x, p); p = fmaf(f0.y, u0.y, p);
            p = fmaf(f1.x, u0.z, p); p = fmaf(f1.y, u0.w, p);
            p = fmaf(f2.x, u1.x, p); p = fmaf(f2.y, u1.y, p);
            p = fmaf(f3.x, u1.z, p); p = fmaf(f3.y, u1.w, p);
        }
#pragma unroll
        for (int o = 16; o > 0; o >>= 1) p += __shfl_xor_sync(0xFFFFFFFFu, p, o);
        if (lane == 0) {
            float e = expf((p + g_d0[bag]) * 0.08838834764831845f);  // 1/sqrt(128)
            g_A[n] = e;
            if (bag != curBag) {
                if (curBag >= 0) atomicAdd(&g_s[curBag], curS);
                curBag = bag; curS = e;
            } else curS += e;
        }
    }
    if (lane == 0 && curBag >= 0) atomicAdd(&g_s[curBag], curS);
}

// -------- K5: Bemb[b,:] += Aw[n] * relu(bf16(feats[n]) @ wvT + b_v) --------
// 128 threads, 4 warps in 2x2, 64x64 warp tiles, 4-stage cp.async ring.
__global__ __launch_bounds__(128, 2) void k5_bemb(const float* __restrict__ b_v)
{
    extern __shared__ char smem[];
    unsigned sA = (unsigned)__cvta_generic_to_shared(smem);           // 4 A bufs
    unsigned sB = sA + 4 * K5_TB;                                     // 4 B bufs
    float* sAw  = (float*)(smem + K5_AW);
    int*   sBag = (int*)(smem + K5_BAG);
    float (*sRed)[128] = (float(*)[128])(smem + K5_RED);

    const int tid = threadIdx.x;
    const int lane = tid & 31, warp = tid >> 5;
    const int gid = lane >> 2, tig = lane & 3;
    const int wm = warp >> 1, wn = warp & 1;     // 2x2 warp grid, 64x64 tiles
    const int col0 = blockIdx.x * 128;
    const int row0 = blockIdx.y * 128;

    {
        int n = row0 + tid;
        int bag = find_bag(n);
        sBag[tid] = bag;
        sAw[tid] = g_A[n] / g_s[bag];
        sRed[0][tid] = 0.f;
        sRed[1][tid] = 0.f;
    }

    float acc[4][8][4];
#pragma unroll
    for (int mi = 0; mi < 4; mi++)
#pragma unroll
        for (int ni = 0; ni < 8; ni++)
#pragma unroll
            for (int q = 0; q < 4; q++) acc[mi][ni][q] = 0.f;

    // loads: one thread per row, 4 cp16 each for A and B per chunk
#define ISSUE5(B, kc)                                                            \
    do {                                                                         \
        const __nv_bfloat16* ga = &g_fbf[(size_t)(row0 + tid) * NF + (kc)];      \
        const __nv_bfloat16* gb = &g_wvT[(size_t)(col0 + tid) * NF + (kc)];      \
        unsigned da = sA + (B) * K5_TB + tid * SROW;                             \
        unsigned db = sB + (B) * K5_TB + tid * SROW;                             \
        cp16(da, ga);      cp16(da + 16, ga + 8);                                \
        cp16(da + 32, ga + 16); cp16(da + 48, ga + 24);                          \
        cp16(db, gb);      cp16(db + 16, gb + 8);                                \
        cp16(db + 32, gb + 16); cp16(db + 48, gb + 24);                          \
        cpcommit();                                                              \
    } while (0)

    ISSUE5(0, 0); ISSUE5(1, KC); ISSUE5(2, 2 * KC);
    for (int ck = 0; ck < NF / KC; ck++) {
        const int buf = ck & 3;
        cpwait2();
        __syncthreads();
        if (ck + 3 < NF / KC) ISSUE5((ck + 3) & 3, (ck + 3) * KC);
        else cpcommit();  // keeps per-thread group count aligned
#pragma unroll
        for (int s = 0; s < 2; s++) {
            const int ks = s * 16;
            unsigned a[4][4], bb[4][4];
#pragma unroll
            for (int mi = 0; mi < 4; mi++) {
                unsigned aaddr = sA + buf * K5_TB
                    + (wm * 64 + mi * 16 + (lane & 15)) * SROW
                    + (ks + ((lane >> 4) << 3)) * 2;
                ldsm4(a[mi], aaddr);
            }
#pragma unroll
            for (int p = 0; p < 4; p++) {
                unsigned baddr = sB + buf * K5_TB
                    + (wn * 64 + p * 16 + (((lane >> 4) & 1) << 3) + (lane & 7)) * SROW
                    + (ks + (((lane >> 3) & 1) << 3)) * 2;
                ldsm4(bb[p], baddr);
            }
#pragma unroll
            for (int mi = 0; mi < 4; mi++)
#pragma unroll
                for (int ni = 0; ni < 8; ni++) {
                    unsigned b0 = bb[ni >> 1][(ni & 1) * 2];
                    unsigned b1 = bb[ni >> 1][(ni & 1) * 2 + 1];
                    mma_bf16(acc[mi][ni], a[mi], b0, b1);
                }
        }
    }
#undef ISSUE5

    // epilogue: relu + bias, weight by Aw, two-bag smem reduction
    const int bag0 = sBag[0];
    const int bag1 = sBag[127];
    __syncthreads();
#pragma unroll
    for (int ni = 0; ni < 8; ni++) {
        int cl = wn * 64 + ni * 8 + 2 * tig;
        float bv0f = __ldg(&b_v[col0 + cl]), bv1f = __ldg(&b_v[col0 + cl + 1]);
        float s00 = 0.f, s01 = 0.f, s10 = 0.f, s11 = 0.f;
#pragma unroll
        for (int mi = 0; mi < 4; mi++) {
#pragma unroll
            for (int h = 0; h < 2; h++) {
                int r = wm * 64 + mi * 16 + gid + 8 * h;
                float w = sAw[r];
                float v0 = fmaxf(acc[mi][ni][2 * h] + bv0f, 0.f) * w;
                float v1 = fmaxf(acc[mi][ni][2 * h + 1] + bv1f, 0.f) * w;
                if (sBag[r] != bag0) { s10 += v0; s11 += v1; }
                else                 { s00 += v0; s01 += v1; }
            }
        }
        atomicAdd(&sRed[0][cl], s00);
        atomicAdd(&sRed[0][cl + 1], s01);
        if (s10 != 0.f) atomicAdd(&sRed[1][cl], s10);
        if (s11 != 0.f) atomicAdd(&sRed[1][cl + 1], s11);
    }
    __syncthreads();
    {
        atomicAdd(&g_Bemb[bag0 * NF + col0 + tid], sRed[0][tid]);
        if (bag1 != bag0) {
            float v = sRed[1][tid];
            if (v != 0.f) atomicAdd(&g_Bemb[bag1 * NF + col0 + tid], v);
        }
    }
}

// -------- K6: bag_pred ------------------------------------------------------
__global__ void k6_pred(const float* __restrict__ fcc_w,
                        const float* __restrict__ fcc_b,
                        float* __restrict__ out)
{
    int b = blockIdx.x;
    int t = threadIdx.x;  // 128
    float p = 0.f;
    for (int k = t; k < NF; k += 128) p = fmaf(g_Bemb[b * NF + k], fcc_w[k], p);
#pragma unroll
    for (int o = 16; o > 0; o >>= 1) p += __shfl_xor_sync(0xFFFFFFFFu, p, o);
    __shared__ float sp[4];
    if ((t & 31) == 0) sp[t >> 5] = p;
    __syncthreads();
    if (t == 0) out[b] = sp[0] + sp[1] + sp[2] + sp[3] + fcc_b[0];
}

// ---------------------------------------------------------------------------
extern "C" void kernel_launch(void* const* d_in, const int* in_sizes, int n_in,
                              void* d_out, int out_size)
{
    const float* feats  = (const float*)d_in[0];
    const int*   split  = (const int*)  d_in[1];
    const float* w_ins  = (const float*)d_in[2];
    const float* b_ins  = (const float*)d_in[3];
    const float* w_q    = (const float*)d_in[4];
    const float* b_q    = (const float*)d_in[5];
    const float* w_v    = (const float*)d_in[6];
    const float* b_v    = (const float*)d_in[7];
    const float* fcc_w  = (const float*)d_in[8];
    const float* fcc_b  = (const float*)d_in[9];
    float* out = (float*)d_out;

    cudaFuncSetAttribute(k5_bemb, cudaFuncAttributeMaxDynamicSharedMemorySize, K5_SM);

    k0_init<<<1, 256>>>(split);                                     // 0
    kt_transpose<<<dim3(NF / 32, NF / 32), dim3(32, 8)>>>(w_v);     // 1
    k_pre<<<NTOT / 64, 256>>>(feats, w_ins, b_ins, out);            // 2
    k3b<<<NBAG, 512>>>(feats, w_q, b_q);                            // 3
    k4_scores<<<NTOT / 64, 256>>>();                                // 4
    k5_bemb<<<dim3(4, NTOT / 128), 128, K5_SM>>>(b_v);              // 5
    k6_pred<<<NBAG, 128>>>(fcc_w, fcc_b, out);                      // 6
}

// round 14
// speedup vs baseline: 1.0359x; 1.0359x over previous
#include <cuda_runtime.h>
#include <cuda_bf16.h>
#include <math.h>

#define NTOT 131072
#define NF   512
#define DQ   128
#define NBAG 32
#define KC   64             // k-chunk (elements)
#define SROW 144            // bytes per smem row (64 bf16 + 16B pad)

// k5 dynamic smem layout (3-stage ring, stage = A tile + B tile)
#define K5_TB   (128 * SROW)            // 18432 B per operand tile
#define K5_STG  (2 * K5_TB)             // 36864 B per stage
#define K5_AW   (3 * K5_STG)            // float[128]
#define K5_BAG  (K5_AW + 512)           // int[128]
#define K5_RED  (K5_BAG + 512)          // float[2][128]
#define K5_SM   (K5_RED + 1024)        // 112640 B

// -------- scratch (static __device__ — no allocations allowed) ----------
__device__ __nv_bfloat16      g_fbf[(size_t)NTOT * NF];   // 128 MB bf16 feats
__device__ float              g_A[NTOT];                   // holds e = exp(A)
__device__ int                g_off[NBAG + 1];
__device__ unsigned long long g_crit[NBAG];
__device__ float              g_s[NBAG];
__device__ float              g_Bemb[NBAG * NF];
__device__ float              g_u[NBAG * NF];              // w_q @ Qc per bag
__device__ float              g_d0[NBAG];                  // b_q . Qc per bag
__device__ __nv_bfloat16      g_wvT[(size_t)NF * NF];      // [col][k]

// -------- helpers -----------------------------------------------------------
__device__ __forceinline__ unsigned fkey(float f) {
    unsigned u = __float_as_uint(f);
    return (u & 0x80000000u) ? ~u : (u | 0x80000000u);
}
__device__ __forceinline__ int find_bag(int n) {
    int lo = 0, hi = NBAG;
    while (hi - lo > 1) {
        int mid = (lo + hi) >> 1;
        if (n >= g_off[mid]) lo = mid; else hi = mid;
    }
    return lo;
}
__device__ __forceinline__ unsigned pk(float lo, float hi) {
    __nv_bfloat162 h = __floats2bfloat162_rn(lo, hi);
    return *(unsigned*)&h;
}
__device__ __forceinline__ void mma_bf16(float d[4], const unsigned a[4],
                                         unsigned b0, unsigned b1) {
    asm volatile(
        "mma.sync.aligned.m16n8k16.row.col.f32.bf16.bf16.f32 "
        "{%0,%1,%2,%3}, {%4,%5,%6,%7}, {%8,%9}, {%0,%1,%2,%3};"
        : "+f"(d[0]), "+f"(d[1]), "+f"(d[2]), "+f"(d[3])
        : "r"(a[0]), "r"(a[1]), "r"(a[2]), "r"(a[3]), "r"(b0), "r"(b1));
}
__device__ __forceinline__ void ldsm4(unsigned r[4], unsigned saddr) {
    asm volatile("ldmatrix.sync.aligned.m8n8.x4.shared.b16 {%0,%1,%2,%3}, [%4];"
                 : "=r"(r[0]), "=r"(r[1]), "=r"(r[2]), "=r"(r[3]) : "r"(saddr));
}
__device__ __forceinline__ void cp16(unsigned sdst, const void* gsrc) {
    asm volatile("cp.async.cg.shared.global [%0], [%1], 16;" :: "r"(sdst), "l"(gsrc));
}
__device__ __forceinline__ void cpcommit() { asm volatile("cp.async.commit_group;"); }
__device__ __forceinline__ void cpwait1()  { asm volatile("cp.async.wait_group 1;"); }

// -------- K0: prefix offsets + reset accumulators --------------------------
__global__ void k0_init(const int* __restrict__ sizes) {
    int t = threadIdx.x;
    if (t == 0) {
        int acc = 0;
        for (int i = 0; i < NBAG; i++) { g_off[i] = acc; acc += sizes[i]; }
        g_off[NBAG] = acc;
    }
    if (t < NBAG) { g_crit[t] = 0ull; g_s[t] = 0.f; }
    for (int i = t; i < NBAG * NF; i += blockDim.x) g_Bemb[i] = 0.f;
}

// -------- KT: transpose fp32 w_v [NF][NF] -> bf16 [col][k] -----------------
__global__ void kt_transpose(const float* __restrict__ src) {
    __shared__ float tile[32][33];
    int c0 = blockIdx.x * 32, r0 = blockIdx.y * 32;
    int x = threadIdx.x, y = threadIdx.y;  // (32,8)
#pragma unroll
    for (int i = 0; i < 32; i += 8)
        tile[y + i][x] = src[(size_t)(r0 + y + i) * NF + c0 + x];
    __syncthreads();
#pragma unroll
    for (int i = 0; i < 32; i += 8)
        g_wvT[(size_t)(c0 + y + i) * NF + r0 + x] = __float2bfloat16_rn(tile[x][y + i]);
}

// -------- K_PRE: feats fp32->bf16, c = feats@w_ins+b (fp32), fused crit ----
__global__ __launch_bounds__(256) void k_pre(
    const float* __restrict__ feats, const float* __restrict__ w_ins,
    const float* __restrict__ b_ins, float* __restrict__ out)
{
    __shared__ float wins[NF];
    int tid = threadIdx.x, lane = tid & 31, warp = tid >> 5;
    for (int i = tid; i < NF; i += 256) wins[i] = w_ins[i];
    __syncthreads();
    const float bi = __ldg(&b_ins[0]);
    const int base = blockIdx.x * 64 + warp * 8;
    int curBag = -1; unsigned curKey = 0u; unsigned curN = 0u;
#pragma unroll
    for (int rr = 0; rr < 8; rr++) {
        int n = base + rr;
        const float4* fp = (const float4*)&feats[(size_t)n * NF];
        uint2* dst = (uint2*)&g_fbf[(size_t)n * NF];
        float c = 0.f;
#pragma unroll
        for (int i = 0; i < 4; i++) {
            int idx = lane + i * 32;
            float4 v = fp[idx];
            int k = idx * 4;
            c = fmaf(v.x, wins[k], c);     c = fmaf(v.y, wins[k + 1], c);
            c = fmaf(v.z, wins[k + 2], c); c = fmaf(v.w, wins[k + 3], c);
            dst[idx] = make_uint2(pk(v.x, v.y), pk(v.z, v.w));
        }
#pragma unroll
        for (int o = 16; o > 0; o >>= 1) c += __shfl_xor_sync(0xFFFFFFFFu, c, o);
        if (lane == 0) {
            float cv = c + bi;
            out[NBAG + n] = cv;
            int bag = find_bag(n);
            unsigned k = fkey(cv);
            if (bag != curBag) {
                if (curBag >= 0)
                    atomicMax(&g_crit[curBag],
                              ((unsigned long long)curKey << 32) | curN);
                curBag = bag; curKey = k; curN = 0xFFFFFFFFu - (unsigned)n;
            } else if (k > curKey) {
                curKey = k; curN = 0xFFFFFFFFu - (unsigned)n;
            }
        }
    }
    if (lane == 0 && curBag >= 0)
        atomicMax(&g_crit[curBag], ((unsigned long long)curKey << 32) | curN);
}

// -------- K3B: per bag: Qc = feats[crit]@w_q + b_q; u = w_q@Qc; d0 = b_q.Qc
__global__ __launch_bounds__(512) void k3b(
    const float* __restrict__ feats, const float* __restrict__ w_q,
    const float* __restrict__ b_q)
{
    __shared__ float sf[NF];
    __shared__ float sq[DQ];
    __shared__ float part[4][DQ];
    const int b = blockIdx.x, t = threadIdx.x;
    const int lane = t & 31, warp = t >> 5;
    const int cr = (int)(0xFFFFFFFFu - (unsigned)(g_crit[b] & 0xFFFFFFFFull));

    if (t < NF) sf[t] = feats[(size_t)cr * NF + t];
    __syncthreads();

    {
        const int col = t & 127, kq = t >> 7;
        float q = 0.f;
        const float* wp = &w_q[(size_t)(kq * 128) * DQ + col];
        const float* fp = &sf[kq * 128];
#pragma unroll 8
        for (int k = 0; k < 128; k++) q = fmaf(fp[k], wp[(size_t)k * DQ], q);
        part[kq][col] = q;
    }
    __syncthreads();
    if (t < DQ) sq[t] = part[0][t] + part[1][t] + part[2][t] + part[3][t] + __ldg(&b_q[t]);
    __syncthreads();

    for (int k = warp; k < NF; k += 16) {
        const float* wr = &w_q[(size_t)k * DQ];
        float s = 0.f;
#pragma unroll
        for (int c = 0; c < 4; c++)
            s = fmaf(wr[lane + 32 * c], sq[lane + 32 * c], s);
#pragma unroll
        for (int o = 16; o > 0; o >>= 1) s += __shfl_xor_sync(0xFFFFFFFFu, s, o);
        if (lane == 0) g_u[b * NF + k] = s;
    }

    if (t < DQ) part[0][t] = __ldg(&b_q[t]) * sq[t];
    __syncthreads();
    if (t < 32) {
        float d = part[0][t] + part[0][t + 32] + part[0][t + 64] + part[0][t + 96];
#pragma unroll
        for (int o = 16; o > 0; o >>= 1) d += __shfl_xor_sync(0xFFFFFFFFu, d, o);
        if (t == 0) g_d0[b] = d;
    }
}

// -------- K4: e[n] = exp((feats[n].u[bag] + d0[bag])/sqrt(dq)); s[bag] += e
__global__ __launch_bounds__(256) void k4_scores() {
    const int warp = threadIdx.x >> 5, lane = threadIdx.x & 31;
    const int base = blockIdx.x * 64 + warp * 8;
    int curBag = -1; float curS = 0.f;
#pragma unroll
    for (int rr = 0; rr < 8; rr++) {
        int n = base + rr;
        int bag = find_bag(n);
        const uint4*  fp = (const uint4*)&g_fbf[(size_t)n * NF];
        const float4* up = (const float4*)&g_u[bag * NF];
        float p = 0.f;
#pragma unroll
        for (int i = 0; i < 2; i++) {
            uint4 fv = fp[lane * 2 + i];
            float4 u0 = up[lane * 4 + i * 2];
            float4 u1 = up[lane * 4 + i * 2 + 1];
            float2 f0 = __bfloat1622float2(*(__nv_bfloat162*)&fv.x);
            float2 f1 = __bfloat1622float2(*(__nv_bfloat162*)&fv.y);
            float2 f2 = __bfloat1622float2(*(__nv_bfloat162*)&fv.z);
            float2 f3 = __bfloat1622float2(*(__nv_bfloat162*)&fv.w);
            p = fmaf(f0.x, u0.x, p); p = fmaf(f0.y, u0.y, p);
            p = fmaf(f1.x, u0.z, p); p = fmaf(f1.y, u0.w, p);
            p = fmaf(f2.x, u1.x, p); p = fmaf(f2.y, u1.y, p);
            p = fmaf(f3.x, u1.z, p); p = fmaf(f3.y, u1.w, p);
        }
#pragma unroll
        for (int o = 16; o > 0; o >>= 1) p += __shfl_xor_sync(0xFFFFFFFFu, p, o);
        if (lane == 0) {
            float e = expf((p + g_d0[bag]) * 0.08838834764831845f);  // 1/sqrt(128)
            g_A[n] = e;
            if (bag != curBag) {
                if (curBag >= 0) atomicAdd(&g_s[curBag], curS);
                curBag = bag; curS = e;
            } else curS += e;
        }
    }
    if (lane == 0 && curBag >= 0) atomicAdd(&g_s[curBag], curS);
}

// -------- K5: Bemb[b,:] += Aw[n] * relu(bf16(feats[n]) @ wvT + b_v) --------
// 256 threads, 8 warps (4x2), 32x64 warp tiles, KC=64, 3-stage cp.async ring.
__global__ __launch_bounds__(256, 2) void k5_bemb(const float* __restrict__ b_v)
{
    extern __shared__ char smem[];
    unsigned s0 = (unsigned)__cvta_generic_to_shared(smem);
    float* sAw  = (float*)(smem + K5_AW);
    int*   sBag = (int*)(smem + K5_BAG);
    float (*sRed)[128] = (float(*)[128])(smem + K5_RED);

    const int tid = threadIdx.x;
    const int lane = tid & 31, warp = tid >> 5;
    const int gid = lane >> 2, tig = lane & 3;
    const int wm = warp >> 1, wn = warp & 1;     // 4x2 warp grid, 32x64 tiles
    const int col0 = blockIdx.x * 128;
    const int row0 = blockIdx.y * 128;
    const int lr = tid >> 1, lkh = (tid & 1) * 32;  // half-row per thread

    if (tid < 128) {
        int n = row0 + tid;
        int bag = find_bag(n);
        sBag[tid] = bag;
        sAw[tid] = g_A[n] / g_s[bag];
    }
    ((float*)sRed)[tid] = 0.f;

    float acc[2][8][4];
#pragma unroll
    for (int mi = 0; mi < 2; mi++)
#pragma unroll
        for (int ni = 0; ni < 8; ni++)
#pragma unroll
            for (int q = 0; q < 4; q++) acc[mi][ni][q] = 0.f;

    // per chunk: thread loads 64B of A (half a row) and 64B of B
#define ISSUE5(STG, kc)                                                          \
    do {                                                                         \
        const __nv_bfloat16* ga = &g_fbf[(size_t)(row0 + lr) * NF + (kc) + lkh]; \
        const __nv_bfloat16* gb = &g_wvT[(size_t)(col0 + lr) * NF + (kc) + lkh]; \
        unsigned da = s0 + (STG) * K5_STG + lr * SROW + lkh * 2;                 \
        unsigned db = s0 + (STG) * K5_STG + K5_TB + lr * SROW + lkh * 2;         \
        cp16(da, ga);      cp16(da + 16, ga + 8);                                \
        cp16(da + 32, ga + 16); cp16(da + 48, ga + 24);                          \
        cp16(db, gb);      cp16(db + 16, gb + 8);                                \
        cp16(db + 32, gb + 16); cp16(db + 48, gb + 24);                          \
        cpcommit();                                                              \
    } while (0)

    ISSUE5(0, 0); ISSUE5(1, KC);
    int stg = 0;
    for (int ck = 0; ck < NF / KC; ck++) {
        cpwait1();
        __syncthreads();
        if (ck + 2 < NF / KC) {
            int ns = stg + 2; if (ns >= 3) ns -= 3;
            ISSUE5(ns, (ck + 2) * KC);
        } else cpcommit();  // keeps per-thread group count aligned
        const unsigned aBase = s0 + stg * K5_STG;
        const unsigned bBase = aBase + K5_TB;
#pragma unroll
        for (int s = 0; s < 4; s++) {
            const int ks = s * 16;
            unsigned a0[4], a1[4], bb[4][4];
            unsigned aaddr = aBase + (wm * 32 + (lane & 15)) * SROW
                           + (ks + ((lane >> 4) << 3)) * 2;
            ldsm4(a0, aaddr);
            ldsm4(a1, aaddr + 16 * SROW);
#pragma unroll
            for (int p = 0; p < 4; p++) {
                unsigned baddr = bBase
                    + (wn * 64 + p * 16 + (((lane >> 4) & 1) << 3) + (lane & 7)) * SROW
                    + (ks + (((lane >> 3) & 1) << 3)) * 2;
                ldsm4(bb[p], baddr);
            }
#pragma unroll
            for (int ni = 0; ni < 8; ni++) {
                unsigned b0 = bb[ni >> 1][(ni & 1) * 2];
                unsigned b1 = bb[ni >> 1][(ni & 1) * 2 + 1];
                mma_bf16(acc[0][ni], a0, b0, b1);
                mma_bf16(acc[1][ni], a1, b0, b1);
            }
        }
        if (++stg == 3) stg = 0;
    }
#undef ISSUE5

    // epilogue: relu + bias, weight by Aw, two-bag smem reduction
    const int bag0 = sBag[0];
    const int bag1 = sBag[127];
    __syncthreads();
#pragma unroll
    for (int ni = 0; ni < 8; ni++) {
        int cl = wn * 64 + ni * 8 + 2 * tig;
        float bv0f = __ldg(&b_v[col0 + cl]), bv1f = __ldg(&b_v[col0 + cl + 1]);
        float s00 = 0.f, s01 = 0.f, s10 = 0.f, s11 = 0.f;
#pragma unroll
        for (int mi = 0; mi < 2; mi++) {
#pragma unroll
            for (int h = 0; h < 2; h++) {
                int r = wm * 32 + mi * 16 + gid + 8 * h;
                float w = sAw[r];
                float v0 = fmaxf(acc[mi][ni][2 * h] + bv0f, 0.f) * w;
                float v1 = fmaxf(acc[mi][ni][2 * h + 1] + bv1f, 0.f) * w;
                if (sBag[r] != bag0) { s10 += v0; s11 += v1; }
                else                 { s00 += v0; s01 += v1; }
            }
        }
        atomicAdd(&sRed[0][cl], s00);
        atomicAdd(&sRed[0][cl + 1], s01);
        if (s10 != 0.f) atomicAdd(&sRed[1][cl], s10);
        if (s11 != 0.f) atomicAdd(&sRed[1][cl + 1], s11);
    }
    __syncthreads();
    if (tid < 128) {
        atomicAdd(&g_Bemb[bag0 * NF + col0 + tid], sRed[0][tid]);
    } else if (bag1 != bag0) {
        float v = sRed[1][tid - 128];
        if (v != 0.f) atomicAdd(&g_Bemb[bag1 * NF + col0 + (tid - 128)], v);
    }
}

// -------- K6: bag_pred ------------------------------------------------------
__global__ void k6_pred(const float* __restrict__ fcc_w,
                        const float* __restrict__ fcc_b,
                        float* __restrict__ out)
{
    int b = blockIdx.x;
    int t = threadIdx.x;  // 128
    float p = 0.f;
    for (int k = t; k < NF; k += 128) p = fmaf(g_Bemb[b * NF + k], fcc_w[k], p);
#pragma unroll
    for (int o = 16; o > 0; o >>= 1) p += __shfl_xor_sync(0xFFFFFFFFu, p, o);
    __shared__ float sp[4];
    if ((t & 31) == 0) sp[t >> 5] = p;
    __syncthreads();
    if (t == 0) out[b] = sp[0] + sp[1] + sp[2] + sp[3] + fcc_b[0];
}

// ---------------------------------------------------------------------------
extern "C" void kernel_launch(void* const* d_in, const int* in_sizes, int n_in,
                              void* d_out, int out_size)
{
    const float* feats  = (const float*)d_in[0];
    const int*   split  = (const int*)  d_in[1];
    const float* w_ins  = (const float*)d_in[2];
    const float* b_ins  = (const float*)d_in[3];
    const float* w_q    = (const float*)d_in[4];
    const float* b_q    = (const float*)d_in[5];
    const float* w_v    = (const float*)d_in[6];
    const float* b_v    = (const float*)d_in[7];
    const float* fcc_w  = (const float*)d_in[8];
    const float* fcc_b  = (const float*)d_in[9];
    float* out = (float*)d_out;

    cudaFuncSetAttribute(k5_bemb, cudaFuncAttributeMaxDynamicSharedMemorySize, K5_SM);

    k0_init<<<1, 256>>>(split);                                     // 0
    kt_transpose<<<dim3(NF / 32, NF / 32), dim3(32, 8)>>>(w_v);     // 1
    k_pre<<<NTOT / 64, 256>>>(feats, w_ins, b_ins, out);            // 2
    k3b<<<NBAG, 512>>>(feats, w_q, b_q);                            // 3
    k4_scores<<<NTOT / 64, 256>>>();                                // 4
    k5_bemb<<<dim3(4, NTOT / 128), 256, K5_SM>>>(b_v);              // 5
    k6_pred<<<NBAG, 128>>>(fcc_w, fcc_b, out);                      // 6
}

// round 15
// speedup vs baseline: 1.0473x; 1.0110x over previous
#include <cuda_runtime.h>
#include <cuda_bf16.h>
#include <math.h>

#define NTOT 131072
#define NF   512
#define DQ   128
#define NBAG 32
#define KC   32
#define SROW 80             // bytes per smem row (k5)

// k5 dynamic smem layout (4-stage ring) — round-12 layout
#define K5_TB   10240                   // 128 rows * 80 B
#define K5_AW   (8 * K5_TB)             // float[128]
#define K5_BAG  (K5_AW + 512)           // int[128]
#define K5_RED  (K5_BAG + 512)          // float[2][128]
#define K5_SM   (K5_RED + 1024)         // 83968 B

// -------- scratch (static __device__ — no allocations allowed) ----------
__device__ __nv_bfloat16      g_fbf[(size_t)NTOT * NF];   // 128 MB bf16 feats
__device__ float              g_A[NTOT];                   // holds e = exp(A)
__device__ int                g_off[NBAG + 1];
__device__ unsigned long long g_crit[NBAG];
__device__ float              g_s[NBAG];
__device__ float              g_Bemb[NBAG * NF];
__device__ float              g_u[NBAG * NF];              // w_q @ Qc per bag
__device__ float              g_d0[NBAG];                  // b_q . Qc per bag
__device__ __nv_bfloat16      g_wvT[(size_t)NF * NF];      // [col][k]

// -------- helpers -----------------------------------------------------------
__device__ __forceinline__ unsigned fkey(float f) {
    unsigned u = __float_as_uint(f);
    return (u & 0x80000000u) ? ~u : (u | 0x80000000u);
}
__device__ __forceinline__ int find_bag(int n) {
    int lo = 0, hi = NBAG;
    while (hi - lo > 1) {
        int mid = (lo + hi) >> 1;
        if (n >= g_off[mid]) lo = mid; else hi = mid;
    }
    return lo;
}
__device__ __forceinline__ unsigned pk(float lo, float hi) {
    __nv_bfloat162 h = __floats2bfloat162_rn(lo, hi);
    return *(unsigned*)&h;
}
__device__ __forceinline__ void mma_bf16(float d[4], const unsigned a[4],
                                         unsigned b0, unsigned b1) {
    asm volatile(
        "mma.sync.aligned.m16n8k16.row.col.f32.bf16.bf16.f32 "
        "{%0,%1,%2,%3}, {%4,%5,%6,%7}, {%8,%9}, {%0,%1,%2,%3};"
        : "+f"(d[0]), "+f"(d[1]), "+f"(d[2]), "+f"(d[3])
        : "r"(a[0]), "r"(a[1]), "r"(a[2]), "r"(a[3]), "r"(b0), "r"(b1));
}
__device__ __forceinline__ void ldsm4(unsigned r[4], unsigned saddr) {
    asm volatile("ldmatrix.sync.aligned.m8n8.x4.shared.b16 {%0,%1,%2,%3}, [%4];"
                 : "=r"(r[0]), "=r"(r[1]), "=r"(r[2]), "=r"(r[3]) : "r"(saddr));
}
__device__ __forceinline__ void cp16(unsigned sdst, const void* gsrc) {
    asm volatile("cp.async.cg.shared.global [%0], [%1], 16;" :: "r"(sdst), "l"(gsrc));
}
__device__ __forceinline__ void cpcommit() { asm volatile("cp.async.commit_group;"); }
__device__ __forceinline__ void cpwait2()  { asm volatile("cp.async.wait_group 2;"); }

// -------- K0: prefix offsets + reset accumulators --------------------------
__global__ void k0_init(const int* __restrict__ sizes) {
    int t = threadIdx.x;
    if (t == 0) {
        int acc = 0;
        for (int i = 0; i < NBAG; i++) { g_off[i] = acc; acc += sizes[i]; }
        g_off[NBAG] = acc;
    }
    if (t < NBAG) { g_crit[t] = 0ull; g_s[t] = 0.f; }
    for (int i = t; i < NBAG * NF; i += blockDim.x) g_Bemb[i] = 0.f;
}

// -------- KT: transpose fp32 w_v [NF][NF] -> bf16 [col][k] -----------------
__global__ void kt_transpose(const float* __restrict__ src) {
    __shared__ float tile[32][33];
    int c0 = blockIdx.x * 32, r0 = blockIdx.y * 32;
    int x = threadIdx.x, y = threadIdx.y;  // (32,8)
#pragma unroll
    for (int i = 0; i < 32; i += 8)
        tile[y + i][x] = src[(size_t)(r0 + y + i) * NF + c0 + x];
    __syncthreads();
#pragma unroll
    for (int i = 0; i < 32; i += 8)
        g_wvT[(size_t)(c0 + y + i) * NF + r0 + x] = __float2bfloat16_rn(tile[x][y + i]);
}

// -------- K_PRE: feats fp32->bf16, c = feats@w_ins+b (fp32), fused crit ----
__global__ __launch_bounds__(256) void k_pre(
    const float* __restrict__ feats, const float* __restrict__ w_ins,
    const float* __restrict__ b_ins, float* __restrict__ out)
{
    __shared__ float wins[NF];
    int tid = threadIdx.x, lane = tid & 31, warp = tid >> 5;
    for (int i = tid; i < NF; i += 256) wins[i] = w_ins[i];
    __syncthreads();
    const float bi = __ldg(&b_ins[0]);
    const int base = blockIdx.x * 64 + warp * 8;
    int curBag = -1; unsigned curKey = 0u; unsigned curN = 0u;
#pragma unroll
    for (int rr = 0; rr < 8; rr++) {
        int n = base + rr;
        const float4* fp = (const float4*)&feats[(size_t)n * NF];
        uint2* dst = (uint2*)&g_fbf[(size_t)n * NF];
        float c = 0.f;
#pragma unroll
        for (int i = 0; i < 4; i++) {
            int idx = lane + i * 32;
            float4 v = fp[idx];
            int k = idx * 4;
            c = fmaf(v.x, wins[k], c);     c = fmaf(v.y, wins[k + 1], c);
            c = fmaf(v.z, wins[k + 2], c); c = fmaf(v.w, wins[k + 3], c);
            dst[idx] = make_uint2(pk(v.x, v.y), pk(v.z, v.w));
        }
#pragma unroll
        for (int o = 16; o > 0; o >>= 1) c += __shfl_xor_sync(0xFFFFFFFFu, c, o);
        if (lane == 0) {
            float cv = c + bi;
            out[NBAG + n] = cv;
            int bag = find_bag(n);
            unsigned k = fkey(cv);
            if (bag != curBag) {
                if (curBag >= 0)
                    atomicMax(&g_crit[curBag],
                              ((unsigned long long)curKey << 32) | curN);
                curBag = bag; curKey = k; curN = 0xFFFFFFFFu - (unsigned)n;
            } else if (k > curKey) {
                curKey = k; curN = 0xFFFFFFFFu - (unsigned)n;
            }
        }
    }
    if (lane == 0 && curBag >= 0)
        atomicMax(&g_crit[curBag], ((unsigned long long)curKey << 32) | curN);
}

// -------- K3B: per bag: Qc = feats[crit]@w_q + b_q; u = w_q@Qc; d0 = b_q.Qc
__global__ __launch_bounds__(512) void k3b(
    const float* __restrict__ feats, const float* __restrict__ w_q,
    const float* __restrict__ b_q)
{
    __shared__ float sf[NF];
    __shared__ float sq[DQ];
    __shared__ float part[4][DQ];
    const int b = blockIdx.x, t = threadIdx.x;
    const int lane = t & 31, warp = t >> 5;
    const int cr = (int)(0xFFFFFFFFu - (unsigned)(g_crit[b] & 0xFFFFFFFFull));

    if (t < NF) sf[t] = feats[(size_t)cr * NF + t];
    __syncthreads();

    // phase 1: Qc[col] — 4 k-quarters x 4 independent chains for MLP
    {
        const int col = t & 127, kq = t >> 7;
        const float* wp = &w_q[(size_t)(kq * 128) * DQ + col];
        const float* fp = &sf[kq * 128];
        float q0 = 0.f, q1 = 0.f, q2 = 0.f, q3 = 0.f;
#pragma unroll 4
        for (int k = 0; k < 32; k++) {
            q0 = fmaf(fp[k],      __ldg(&wp[(size_t)k * DQ]),        q0);
            q1 = fmaf(fp[32 + k], __ldg(&wp[(size_t)(32 + k) * DQ]), q1);
            q2 = fmaf(fp[64 + k], __ldg(&wp[(size_t)(64 + k) * DQ]), q2);
            q3 = fmaf(fp[96 + k], __ldg(&wp[(size_t)(96 + k) * DQ]), q3);
        }
        part[kq][col] = (q0 + q1) + (q2 + q3);
    }
    __syncthreads();
    if (t < DQ) sq[t] = part[0][t] + part[1][t] + part[2][t] + part[3][t] + __ldg(&b_q[t]);
    __syncthreads();

    // phase 2: u[k] = w_q[k,:] . Qc — warp per row, lanes over columns
    for (int k = warp; k < NF; k += 16) {
        const float* wr = &w_q[(size_t)k * DQ];
        float s = 0.f;
#pragma unroll
        for (int c = 0; c < 4; c++)
            s = fmaf(wr[lane + 32 * c], sq[lane + 32 * c], s);
#pragma unroll
        for (int o = 16; o > 0; o >>= 1) s += __shfl_xor_sync(0xFFFFFFFFu, s, o);
        if (lane == 0) g_u[b * NF + k] = s;
    }

    // phase 3: d0 = b_q . Qc
    if (t < DQ) part[0][t] = __ldg(&b_q[t]) * sq[t];
    __syncthreads();
    if (t < 32) {
        float d = part[0][t] + part[0][t + 32] + part[0][t + 64] + part[0][t + 96];
#pragma unroll
        for (int o = 16; o > 0; o >>= 1) d += __shfl_xor_sync(0xFFFFFFFFu, d, o);
        if (t == 0) g_d0[b] = d;
    }
}

// -------- K4: e[n] = exp((feats[n].u[bag] + d0[bag])/sqrt(dq)); s[bag] += e
__global__ __launch_bounds__(256) void k4_scores() {
    const int warp = threadIdx.x >> 5, lane = threadIdx.x & 31;
    const int base = blockIdx.x * 64 + warp * 8;
    int curBag = -1; float curS = 0.f;
#pragma unroll
    for (int rr = 0; rr < 8; rr++) {
        int n = base + rr;
        int bag = find_bag(n);
        const uint4*  fp = (const uint4*)&g_fbf[(size_t)n * NF];
        const float4* up = (const float4*)&g_u[bag * NF];
        float p = 0.f;
#pragma unroll
        for (int i = 0; i < 2; i++) {
            uint4 fv = fp[lane * 2 + i];
            float4 u0 = up[lane * 4 + i * 2];
            float4 u1 = up[lane * 4 + i * 2 + 1];
            float2 f0 = __bfloat1622float2(*(__nv_bfloat162*)&fv.x);
            float2 f1 = __bfloat1622float2(*(__nv_bfloat162*)&fv.y);
            float2 f2 = __bfloat1622float2(*(__nv_bfloat162*)&fv.z);
            float2 f3 = __bfloat1622float2(*(__nv_bfloat162*)&fv.w);
            p = fmaf(f0.x, u0.x, p); p = fmaf(f0.y, u0.y, p);
            p = fmaf(f1.x, u0.z, p); p = fmaf(f1.y, u0.w, p);
            p = fmaf(f2.x, u1.x, p); p = fmaf(f2.y, u1.y, p);
            p = fmaf(f3.x, u1.z, p); p = fmaf(f3.y, u1.w, p);
        }
#pragma unroll
        for (int o = 16; o > 0; o >>= 1) p += __shfl_xor_sync(0xFFFFFFFFu, p, o);
        if (lane == 0) {
            float e = expf((p + g_d0[bag]) * 0.08838834764831845f);  // 1/sqrt(128)
            g_A[n] = e;
            if (bag != curBag) {
                if (curBag >= 0) atomicAdd(&g_s[curBag], curS);
                curBag = bag; curS = e;
            } else curS += e;
        }
    }
    if (lane == 0 && curBag >= 0) atomicAdd(&g_s[curBag], curS);
}

// -------- K5: Bemb[b,:] += Aw[n] * relu(bf16(feats[n]) @ wvT + b_v) --------
// Persistent: grid (4, 74) = 296 CTAs = 2/SM; each loops over row-tiles.
// Mainloop identical to round-12 (KC=32, 4-stage ring, 8 warps, 32x64 tiles).
__global__ __launch_bounds__(256, 2) void k5_bemb(const float* __restrict__ b_v)
{
    extern __shared__ char smem[];
    unsigned sA = (unsigned)__cvta_generic_to_shared(smem);           // 4 A bufs
    unsigned sB = sA + 4 * K5_TB;                                     // 4 B bufs
    float* sAw  = (float*)(smem + K5_AW);
    int*   sBag = (int*)(smem + K5_BAG);
    float (*sRed)[128] = (float(*)[128])(smem + K5_RED);

    const int tid = threadIdx.x;
    const int lane = tid & 31, warp = tid >> 5;
    const int gid = lane >> 2, tig = lane & 3;
    const int wm = warp >> 1, wn = warp & 1;
    const int col0 = blockIdx.x * 128;
    const int lr = tid >> 1, lkh = (tid & 1) * 16;

    for (int tIdx = blockIdx.y; tIdx < NTOT / 128; tIdx += gridDim.y) {
        const int row0 = tIdx * 128;

        if (tid < 128) {
            int n = row0 + tid;
            int bag = find_bag(n);
            sBag[tid] = bag;
            sAw[tid] = g_A[n] / g_s[bag];
        }
        ((float*)sRed)[tid] = 0.f;

        float acc[2][8][4];
#pragma unroll
        for (int mi = 0; mi < 2; mi++)
#pragma unroll
            for (int ni = 0; ni < 8; ni++)
#pragma unroll
                for (int q = 0; q < 4; q++) acc[mi][ni][q] = 0.f;

#define ISSUE5(B, kc)                                                            \
    do {                                                                         \
        const __nv_bfloat16* ga = &g_fbf[(size_t)(row0 + lr) * NF + (kc) + lkh]; \
        const __nv_bfloat16* gb = &g_wvT[(size_t)(col0 + lr) * NF + (kc) + lkh]; \
        unsigned da = sA + (B) * K5_TB + lr * SROW + lkh * 2;                    \
        unsigned db = sB + (B) * K5_TB + lr * SROW + lkh * 2;                    \
        cp16(da, ga); cp16(da + 16, ga + 8);                                     \
        cp16(db, gb); cp16(db + 16, gb + 8);                                     \
        cpcommit();                                                              \
    } while (0)

        ISSUE5(0, 0); ISSUE5(1, KC); ISSUE5(2, 2 * KC);
        for (int ck = 0; ck < NF / KC; ck++) {
            const int buf = ck & 3;
            cpwait2();
            __syncthreads();
            if (ck + 3 < NF / KC) ISSUE5((ck + 3) & 3, (ck + 3) * KC);
            else cpcommit();  // keeps per-thread group count aligned
#pragma unroll
            for (int s = 0; s < 2; s++) {
                const int ks = s * 16;
                unsigned a0[4], a1[4], bb[4][4];
                unsigned aaddr = sA + buf * K5_TB + (wm * 32 + (lane & 15)) * SROW
                               + (ks + ((lane >> 4) << 3)) * 2;
                ldsm4(a0, aaddr);
                ldsm4(a1, aaddr + 16 * SROW);
#pragma unroll
                for (int p = 0; p < 4; p++) {
                    unsigned baddr = sB + buf * K5_TB
                        + (wn * 64 + p * 16 + (((lane >> 4) & 1) << 3) + (lane & 7)) * SROW
                        + (ks + (((lane >> 3) & 1) << 3)) * 2;
                    ldsm4(bb[p], baddr);
                }
#pragma unroll
                for (int ni = 0; ni < 8; ni++) {
                    unsigned b0 = bb[ni >> 1][(ni & 1) * 2];
                    unsigned b1 = bb[ni >> 1][(ni & 1) * 2 + 1];
                    mma_bf16(acc[0][ni], a0, b0, b1);
                    mma_bf16(acc[1][ni], a1, b0, b1);
                }
            }
        }
#undef ISSUE5

        // epilogue: relu + bias, weight by Aw, two-bag smem reduction
        const int bag0 = sBag[0];
        const int bag1 = sBag[127];
        __syncthreads();
#pragma unroll
        for (int ni = 0; ni < 8; ni++) {
            int cl = wn * 64 + ni * 8 + 2 * tig;
            float bv0f = __ldg(&b_v[col0 + cl]), bv1f = __ldg(&b_v[col0 + cl + 1]);
            float s00 = 0.f, s01 = 0.f, s10 = 0.f, s11 = 0.f;
#pragma unroll
            for (int mi = 0; mi < 2; mi++) {
#pragma unroll
                for (int h = 0; h < 2; h++) {
                    int r = wm * 32 + mi * 16 + gid + 8 * h;
                    float w = sAw[r];
                    float v0 = fmaxf(acc[mi][ni][2 * h] + bv0f, 0.f) * w;
                    float v1 = fmaxf(acc[mi][ni][2 * h + 1] + bv1f, 0.f) * w;
                    if (sBag[r] != bag0) { s10 += v0; s11 += v1; }
                    else                 { s00 += v0; s01 += v1; }
                }
            }
            atomicAdd(&sRed[0][cl], s00);
            atomicAdd(&sRed[0][cl + 1], s01);
            if (s10 != 0.f) atomicAdd(&sRed[1][cl], s10);
            if (s11 != 0.f) atomicAdd(&sRed[1][cl + 1], s11);
        }
        __syncthreads();
        if (tid < 128) {
            atomicAdd(&g_Bemb[bag0 * NF + col0 + tid], sRed[0][tid]);
        } else if (bag1 != bag0) {
            float v = sRed[1][tid - 128];
            if (v != 0.f) atomicAdd(&g_Bemb[bag1 * NF + col0 + (tid - 128)], v);
        }
        __syncthreads();   // protect sRed/sAw/sBag before next tile re-init
    }
}

// -------- K6: bag_pred ------------------------------------------------------
__global__ void k6_pred(const float* __restrict__ fcc_w,
                        const float* __restrict__ fcc_b,
                        float* __restrict__ out)
{
    int b = blockIdx.x;
    int t = threadIdx.x;  // 128
    float p = 0.f;
    for (int k = t; k < NF; k += 128) p = fmaf(g_Bemb[b * NF + k], fcc_w[k], p);
#pragma unroll
    for (int o = 16; o > 0; o >>= 1) p += __shfl_xor_sync(0xFFFFFFFFu, p, o);
    __shared__ float sp[4];
    if ((t & 31) == 0) sp[t >> 5] = p;
    __syncthreads();
    if (t == 0) out[b] = sp[0] + sp[1] + sp[2] + sp[3] + fcc_b[0];
}

// ---------------------------------------------------------------------------
extern "C" void kernel_launch(void* const* d_in, const int* in_sizes, int n_in,
                              void* d_out, int out_size)
{
    const float* feats  = (const float*)d_in[0];
    const int*   split  = (const int*)  d_in[1];
    const float* w_ins  = (const float*)d_in[2];
    const float* b_ins  = (const float*)d_in[3];
    const float* w_q    = (const float*)d_in[4];
    const float* b_q    = (const float*)d_in[5];
    const float* w_v    = (const float*)d_in[6];
    const float* b_v    = (const float*)d_in[7];
    const float* fcc_w  = (const float*)d_in[8];
    const float* fcc_b  = (const float*)d_in[9];
    float* out = (float*)d_out;

    cudaFuncSetAttribute(k5_bemb, cudaFuncAttributeMaxDynamicSharedMemorySize, K5_SM);

    k0_init<<<1, 256>>>(split);                                     // 0
    kt_transpose<<<dim3(NF / 32, NF / 32), dim3(32, 8)>>>(w_v);     // 1
    k_pre<<<NTOT / 64, 256>>>(feats, w_ins, b_ins, out);            // 2
    k3b<<<NBAG, 512>>>(feats, w_q, b_q);                            // 3
    k4_scores<<<NTOT / 64, 256>>>();                                // 4
    k5_bemb<<<dim3(4, 74), 256, K5_SM>>>(b_v);                      // 5
    k6_pred<<<NBAG, 128>>>(fcc_w, fcc_b, out);                      // 6
}